// round 1
// baseline (speedup 1.0000x reference)
#include <cuda_runtime.h>
#include <cuda_bf16.h>

// Problem constants
#define BATCH 4
#define SEQ   512
#define DMODEL 64
#define HEADS 8
#define DH 8
#define DFF 256
#define NROW (BATCH*SEQ)          // 2048
#define NELEM (NROW*DMODEL)       // 131072

// ---------------- device scratch (no allocation allowed) ----------------
__device__ float g_y  [NELEM];
__device__ float g_ys [NELEM];
__device__ float g_k  [6][NELEM];
__device__ float g_q  [NELEM];   // [B,H,S,8]
__device__ float g_kk [NELEM];   // [B,H,S,8]
__device__ float g_v  [NELEM];   // [B,H,S,8]
__device__ float g_attp[NELEM];  // pre-projection attention, [B,S,H*8]
__device__ float g_att [NELEM];  // after output projection, [B,S,64]

// ---------------- init: y = x ----------------
__global__ void k_init(const float* __restrict__ x) {
    int i = blockIdx.x * blockDim.x + threadIdx.x;
    for (; i < NELEM; i += gridDim.x * blockDim.x) g_y[i] = x[i];
}

// ---------------- stage combine + QKV projection ----------------
// ys = y + sum_j c_j * k_j  (c_j premultiplied by DT on host; unused c_j = 0)
// q/k/v = ys @ W + b, stored [B,H,S,8]
__global__ void k_combine_qkv(float c1, float c2, float c3, float c4, float c5,
                              const float* __restrict__ Wq, const float* __restrict__ bq,
                              const float* __restrict__ Wk, const float* __restrict__ bk,
                              const float* __restrict__ Wv, const float* __restrict__ bv) {
    __shared__ float ys_s[32 * 64];
    const int row0 = blockIdx.x * 32;
    const int tid  = threadIdx.x;

    for (int i = tid; i < 32 * 64; i += 256) {
        int gi = row0 * 64 + i;
        float v = g_y[gi];
        v = fmaf(c1, g_k[0][gi], v);
        v = fmaf(c2, g_k[1][gi], v);
        v = fmaf(c3, g_k[2][gi], v);
        v = fmaf(c4, g_k[3][gi], v);
        v = fmaf(c5, g_k[4][gi], v);
        ys_s[i] = v;
        g_ys[gi] = v;
    }
    __syncthreads();

    const int c  = tid & 63;
    const int ty = tid >> 6;   // 0..3, rows ty + 4*j

    float accq[8], acck[8], accv[8];
#pragma unroll
    for (int j = 0; j < 8; j++) { accq[j] = 0.f; acck[j] = 0.f; accv[j] = 0.f; }

    for (int kk = 0; kk < 64; kk++) {
        float wq = Wq[kk * 64 + c];
        float wk = Wk[kk * 64 + c];
        float wv = Wv[kk * 64 + c];
#pragma unroll
        for (int j = 0; j < 8; j++) {
            float yv = ys_s[(ty + 4 * j) * 64 + kk];
            accq[j] = fmaf(yv, wq, accq[j]);
            acck[j] = fmaf(yv, wk, acck[j]);
            accv[j] = fmaf(yv, wv, accv[j]);
        }
    }

    const int h = c >> 3, dd = c & 7;
    const float bqv = bq[c], bkv = bk[c], bvv = bv[c];
#pragma unroll
    for (int j = 0; j < 8; j++) {
        int r = row0 + ty + 4 * j;
        int b = r >> 9;           // /512
        int s = r & 511;
        int idx = ((b * HEADS + h) * SEQ + s) * DH + dd;
        g_q [idx] = accq[j] + bqv;
        g_kk[idx] = acck[j] + bkv;
        g_v [idx] = accv[j] + bvv;
    }
}

// ---------------- attention ----------------
// grid: 32 (b,h) pairs * 4 query tiles of 128. 256 threads: 128 queries x 2 key halves.
__global__ void k_attn() {
    __shared__ float Ks[SEQ * DH];
    __shared__ float Vs[SEQ * DH];
    __shared__ float sm_m[128], sm_l[128], sm_o[128][8];

    const int blk = blockIdx.x;
    const int bh  = blk >> 2;     // 0..31
    const int qt  = blk & 3;
    const int tid = threadIdx.x;

    const float* Kg = g_kk + bh * (SEQ * DH);
    const float* Vg = g_v  + bh * (SEQ * DH);
    for (int i = tid; i < SEQ * DH; i += 256) { Ks[i] = Kg[i]; Vs[i] = Vg[i]; }
    __syncthreads();

    const int qi   = tid & 127;
    const int half = tid >> 7;
    const int qs   = qt * 128 + qi;
    const float scale = 0.35355339059327373f; // 1/sqrt(8)

    float qreg[8];
    const float* qg = g_q + bh * (SEQ * DH) + qs * DH;
#pragma unroll
    for (int j = 0; j < 8; j++) qreg[j] = qg[j] * scale;

    float m = -1e30f, l = 0.f, o[8];
#pragma unroll
    for (int j = 0; j < 8; j++) o[j] = 0.f;

    const int k0base = half * 256;
    for (int k0 = k0base; k0 < k0base + 256; k0 += 8) {
        float s[8];
        float cmax = -1e30f;
#pragma unroll
        for (int u = 0; u < 8; u++) {
            const float4* kp4 = reinterpret_cast<const float4*>(&Ks[(k0 + u) * 8]);
            float4 ka = kp4[0], kb = kp4[1];
            float a = 0.f;
            a = fmaf(qreg[0], ka.x, a); a = fmaf(qreg[1], ka.y, a);
            a = fmaf(qreg[2], ka.z, a); a = fmaf(qreg[3], ka.w, a);
            a = fmaf(qreg[4], kb.x, a); a = fmaf(qreg[5], kb.y, a);
            a = fmaf(qreg[6], kb.z, a); a = fmaf(qreg[7], kb.w, a);
            s[u] = a;
            cmax = fmaxf(cmax, a);
        }
        if (cmax > m) {
            float al = __expf(m - cmax);
            l *= al;
#pragma unroll
            for (int j = 0; j < 8; j++) o[j] *= al;
            m = cmax;
        }
#pragma unroll
        for (int u = 0; u < 8; u++) {
            float p = __expf(s[u] - m);
            l += p;
            const float4* vp4 = reinterpret_cast<const float4*>(&Vs[(k0 + u) * 8]);
            float4 va = vp4[0], vb = vp4[1];
            o[0] = fmaf(p, va.x, o[0]); o[1] = fmaf(p, va.y, o[1]);
            o[2] = fmaf(p, va.z, o[2]); o[3] = fmaf(p, va.w, o[3]);
            o[4] = fmaf(p, vb.x, o[4]); o[5] = fmaf(p, vb.y, o[5]);
            o[6] = fmaf(p, vb.z, o[6]); o[7] = fmaf(p, vb.w, o[7]);
        }
    }

    if (half == 1) {
        sm_m[qi] = m; sm_l[qi] = l;
#pragma unroll
        for (int j = 0; j < 8; j++) sm_o[qi][j] = o[j];
    }
    __syncthreads();
    if (half == 0) {
        float m2 = sm_m[qi], l2 = sm_l[qi];
        float M  = fmaxf(m, m2);
        float a1 = __expf(m - M), a2 = __expf(m2 - M);
        float L  = l * a1 + l2 * a2;
        float inv = 1.f / L;
        int b = bh >> 3, h = bh & 7;
        float* op = g_attp + ((b * SEQ + qs) * DMODEL) + h * DH;
#pragma unroll
        for (int j = 0; j < 8; j++) op[j] = (o[j] * a1 + sm_o[qi][j] * a2) * inv;
    }
}

// ---------------- output projection: att = attp @ Wo + bo ----------------
__global__ void k_oproj(const float* __restrict__ Wo, const float* __restrict__ bo) {
    __shared__ float in_s[32 * 64];
    const int row0 = blockIdx.x * 32;
    const int tid  = threadIdx.x;

    for (int i = tid; i < 32 * 64; i += 256) in_s[i] = g_attp[row0 * 64 + i];
    __syncthreads();

    const int c  = tid & 63;
    const int ty = tid >> 6;
    float acc[8];
#pragma unroll
    for (int j = 0; j < 8; j++) acc[j] = 0.f;

    for (int kk = 0; kk < 64; kk++) {
        float w = Wo[kk * 64 + c];
#pragma unroll
        for (int j = 0; j < 8; j++)
            acc[j] = fmaf(in_s[(ty + 4 * j) * 64 + kk], w, acc[j]);
    }
    const float bov = bo[c];
#pragma unroll
    for (int j = 0; j < 8; j++)
        g_att[(row0 + ty + 4 * j) * 64 + c] = acc[j] + bov;
}

// ---------------- FFN: k_stage = att + relu((ys+att)@W1+b1)@W2 + b2 ----------------
__global__ void k_ffn(const float* __restrict__ W1, const float* __restrict__ b1,
                      const float* __restrict__ W2, const float* __restrict__ b2,
                      int stage) {
    __shared__ float z_s[16 * 64];
    __shared__ float h_s[16 * 256];
    const int row0 = blockIdx.x * 16;
    const int tid  = threadIdx.x;

    for (int i = tid; i < 16 * 64; i += 256) {
        int gi = row0 * 64 + i;
        z_s[i] = g_ys[gi] + g_att[gi];
    }
    __syncthreads();

    {   // h = relu(z @ W1 + b1) ; thread = one of 256 columns, 16 rows each
        float acc[16];
#pragma unroll
        for (int r = 0; r < 16; r++) acc[r] = 0.f;
        for (int kk = 0; kk < 64; kk++) {
            float w = W1[kk * 256 + tid];
#pragma unroll
            for (int r = 0; r < 16; r++)
                acc[r] = fmaf(z_s[r * 64 + kk], w, acc[r]);
        }
        float bb = b1[tid];
#pragma unroll
        for (int r = 0; r < 16; r++)
            h_s[r * 256 + tid] = fmaxf(acc[r] + bb, 0.f);
    }
    __syncthreads();

    {   // out = h @ W2 + b2 ; k_stage = att + out
        const int c  = tid & 63;
        const int ty = tid >> 6;
        float acc[4] = {0.f, 0.f, 0.f, 0.f};
        for (int kk = 0; kk < 256; kk++) {
            float w = W2[kk * 64 + c];
#pragma unroll
            for (int j = 0; j < 4; j++)
                acc[j] = fmaf(h_s[(ty + 4 * j) * 256 + kk], w, acc[j]);
        }
        float bb = b2[c];
        float* kout = g_k[stage];
#pragma unroll
        for (int j = 0; j < 4; j++) {
            int gi = (row0 + ty + 4 * j) * 64 + c;
            kout[gi] = g_att[gi] + acc[j] + bb;
        }
    }
}

// ---------------- RK step update ----------------
__global__ void k_update(float d1, float d2, float d3, float d4, float d5, float d6,
                         float* dout) {
    int i = blockIdx.x * blockDim.x + threadIdx.x;
    for (; i < NELEM; i += gridDim.x * blockDim.x) {
        float v = g_y[i];
        v = fmaf(d1, g_k[0][i], v);
        v = fmaf(d2, g_k[1][i], v);
        v = fmaf(d3, g_k[2][i], v);
        v = fmaf(d4, g_k[3][i], v);
        v = fmaf(d5, g_k[4][i], v);
        v = fmaf(d6, g_k[5][i], v);
        if (dout) dout[i] = v;
        else      g_y[i]  = v;
    }
}

// ---------------- host launcher ----------------
extern "C" void kernel_launch(void* const* d_in, const int* in_sizes, int n_in,
                              void* d_out, int out_size) {
    const float* x  = (const float*)d_in[0];
    // d_in[1] = mask : additive, broadcast over key axis -> softmax-invariant, skipped
    const float* Wq = (const float*)d_in[2];
    const float* bq = (const float*)d_in[3];
    const float* Wk = (const float*)d_in[4];
    const float* bk = (const float*)d_in[5];
    const float* Wv = (const float*)d_in[6];
    const float* bv = (const float*)d_in[7];
    const float* Wo = (const float*)d_in[8];
    const float* bo = (const float*)d_in[9];
    const float* W1 = (const float*)d_in[10];
    const float* b1 = (const float*)d_in[11];
    const float* W2 = (const float*)d_in[12];
    const float* b2 = (const float*)d_in[13];
    float* out = (float*)d_out;

    const double DT = 0.25;
    // Stage coefficients (a_ij) premultiplied by DT; zero-padded to 5 entries.
    const float C[6][5] = {
        {0.f, 0.f, 0.f, 0.f, 0.f},
        {(float)(DT * 0.25), 0.f, 0.f, 0.f, 0.f},
        {(float)(DT * 3.0 / 32.0),     (float)(DT * 9.0 / 32.0), 0.f, 0.f, 0.f},
        {(float)(DT * 1932.0 / 2197.0), (float)(DT * -7200.0 / 2197.0),
         (float)(DT * 7296.0 / 2197.0), 0.f, 0.f},
        {(float)(DT * 439.0 / 216.0),  (float)(DT * -8.0),
         (float)(DT * 3680.0 / 513.0), (float)(DT * -845.0 / 4104.0), 0.f},
        {(float)(DT * -8.0 / 27.0),    (float)(DT * 2.0),
         (float)(DT * -3544.0 / 2565.0), (float)(DT * 1859.0 / 4104.0),
         (float)(DT * -11.0 / 40.0)}
    };
    const float Bc[6] = {
        (float)(DT * 16.0 / 135.0), 0.f,
        (float)(DT * 6656.0 / 12825.0),
        (float)(DT * 28561.0 / 56430.0),
        (float)(DT * -9.0 / 50.0),
        (float)(DT * 2.0 / 55.0)
    };

    k_init<<<128, 256>>>(x);

    const int n_steps = 4;
    for (int step = 0; step < n_steps; ++step) {
        for (int st = 0; st < 6; ++st) {
            k_combine_qkv<<<64, 256>>>(C[st][0], C[st][1], C[st][2], C[st][3], C[st][4],
                                       Wq, bq, Wk, bk, Wv, bv);
            k_attn<<<128, 256>>>();
            k_oproj<<<64, 256>>>(Wo, bo);
            k_ffn<<<128, 256>>>(W1, b1, W2, b2, st);
        }
        k_update<<<256, 256>>>(Bc[0], Bc[1], Bc[2], Bc[3], Bc[4], Bc[5],
                               (step == n_steps - 1) ? out : nullptr);
    }
}

// round 2
// speedup vs baseline: 1.5726x; 1.5726x over previous
#include <cuda_runtime.h>

#define SEQ    512
#define NROW   2048          // B*S = 4*512
#define NELEM  (NROW*64)

// ---------------- device scratch ----------------
__device__ float g_y   [NELEM];
__device__ float g_ys  [NELEM];
__device__ float g_kbuf[6][NELEM];
__device__ float g_q   [NELEM];   // [B,H,S,8]
__device__ float g_kk  [NELEM];   // [B,H,S,8]
__device__ float g_v   [NELEM];   // [B,H,S,8]
__device__ float g_attp[NELEM];   // [B,S,64] pre-projection attention

__device__ unsigned        g_cnt;
__device__ volatile unsigned g_gen;

// RK coefficients premultiplied by DT=0.25
__constant__ float d_C[6][5] = {
    {0.f, 0.f, 0.f, 0.f, 0.f},
    {(float)(0.25*0.25), 0.f, 0.f, 0.f, 0.f},
    {(float)(0.25*3.0/32.0), (float)(0.25*9.0/32.0), 0.f, 0.f, 0.f},
    {(float)(0.25*1932.0/2197.0), (float)(0.25*-7200.0/2197.0),
     (float)(0.25*7296.0/2197.0), 0.f, 0.f},
    {(float)(0.25*439.0/216.0), (float)(0.25*-8.0),
     (float)(0.25*3680.0/513.0), (float)(0.25*-845.0/4104.0), 0.f},
    {(float)(0.25*-8.0/27.0), (float)(0.25*2.0),
     (float)(0.25*-3544.0/2565.0), (float)(0.25*1859.0/4104.0),
     (float)(0.25*-11.0/40.0)}
};
__constant__ float d_B[6] = {
    (float)(0.25*16.0/135.0), 0.f,
    (float)(0.25*6656.0/12825.0),
    (float)(0.25*28561.0/56430.0),
    (float)(0.25*-9.0/50.0),
    (float)(0.25*2.0/55.0)
};

// ---------------- grid barrier ----------------
__device__ __forceinline__ void gsync(unsigned& gen) {
    __syncthreads();
    if (threadIdx.x == 0) {
        __threadfence();
        if (atomicAdd(&g_cnt, 1u) == gridDim.x - 1) {
            g_cnt = 0;
            __threadfence();
            g_gen = gen + 1;
        } else {
            while (g_gen == gen) __nanosleep(40);
            __threadfence();
        }
    }
    __syncthreads();
    gen++;
}

// ---------------- QKV projection from an 8x64 smem tile ----------------
__device__ __forceinline__ void qkv_from_smem(
        const float* __restrict__ ys_s, int row0,
        const float* __restrict__ Wq, const float* __restrict__ bq,
        const float* __restrict__ Wk, const float* __restrict__ bk,
        const float* __restrict__ Wv, const float* __restrict__ bv) {
    int t = threadIdx.x;
    if (t < 192) {
        int mat = t >> 6, c = t & 63;
        const float* W  = (mat == 0) ? Wq : (mat == 1) ? Wk : Wv;
        const float* bb = (mat == 0) ? bq : (mat == 1) ? bk : bv;
        float* dst      = (mat == 0) ? g_q : (mat == 1) ? g_kk : g_v;
        float acc[8];
#pragma unroll
        for (int r = 0; r < 8; r++) acc[r] = 0.f;
#pragma unroll 8
        for (int kk = 0; kk < 64; kk++) {
            float w = W[kk * 64 + c];
#pragma unroll
            for (int r = 0; r < 8; r++)
                acc[r] = fmaf(ys_s[r * 64 + kk], w, acc[r]);
        }
        float bval = bb[c];
        int h = c >> 3, dd = c & 7;
#pragma unroll
        for (int r = 0; r < 8; r++) {
            int gr = row0 + r;
            int b  = gr >> 9, s = gr & 511;
            dst[((b * 8 + h) * SEQ + s) * 8 + dd] = acc[r] + bval;
        }
    }
}

// ---------------- attention for one (b,h,qtile-of-64) unit ----------------
__device__ __forceinline__ void attn_unit(int unit, float* __restrict__ sm) {
    float* Ks = sm;          // 4096 floats
    float* Vs = sm + 4096;   // 4096 floats
    const int bh = unit >> 3;
    const int qt = unit & 7;
    const int tid = threadIdx.x;

    const float* Kg = g_kk + bh * (SEQ * 8);
    const float* Vg = g_v  + bh * (SEQ * 8);
    {
        const float4* K4 = (const float4*)Kg;
        const float4* V4 = (const float4*)Vg;
        float4* Ks4 = (float4*)Ks;
        float4* Vs4 = (float4*)Vs;
        for (int i = tid; i < 1024; i += 256) { Ks4[i] = K4[i]; Vs4[i] = V4[i]; }
    }
    __syncthreads();

    const int q   = tid >> 2;
    const int seg = tid & 3;
    const int qs  = qt * 64 + q;
    const float scale = 0.35355339059327373f;

    float qreg[8];
    {
        const float4* qg = (const float4*)(g_q + (bh * SEQ + qs) * 8);
        float4 qa = qg[0], qb = qg[1];
        qreg[0]=qa.x*scale; qreg[1]=qa.y*scale; qreg[2]=qa.z*scale; qreg[3]=qa.w*scale;
        qreg[4]=qb.x*scale; qreg[5]=qb.y*scale; qreg[6]=qb.z*scale; qreg[7]=qb.w*scale;
    }

    float m = -1e30f, l = 0.f, o[8];
#pragma unroll
    for (int j = 0; j < 8; j++) o[j] = 0.f;

    // interleaved keys: this thread handles k = seg + 4*i  (bank-conflict-free)
    for (int i0 = 0; i0 < 128; i0 += 8) {
        float s[8];
        float cmax = -1e30f;
#pragma unroll
        for (int u = 0; u < 8; u++) {
            int k = seg + 4 * (i0 + u);
            const float4* kp = (const float4*)&Ks[k * 8];
            float4 ka = kp[0], kb = kp[1];
            float a = 0.f;
            a = fmaf(qreg[0], ka.x, a); a = fmaf(qreg[1], ka.y, a);
            a = fmaf(qreg[2], ka.z, a); a = fmaf(qreg[3], ka.w, a);
            a = fmaf(qreg[4], kb.x, a); a = fmaf(qreg[5], kb.y, a);
            a = fmaf(qreg[6], kb.z, a); a = fmaf(qreg[7], kb.w, a);
            s[u] = a;
            cmax = fmaxf(cmax, a);
        }
        if (cmax > m) {
            float al = __expf(m - cmax);
            l *= al;
#pragma unroll
            for (int j = 0; j < 8; j++) o[j] *= al;
            m = cmax;
        }
#pragma unroll
        for (int u = 0; u < 8; u++) {
            float p = __expf(s[u] - m);
            l += p;
            int k = seg + 4 * (i0 + u);
            const float4* vp = (const float4*)&Vs[k * 8];
            float4 va = vp[0], vb = vp[1];
            o[0] = fmaf(p, va.x, o[0]); o[1] = fmaf(p, va.y, o[1]);
            o[2] = fmaf(p, va.z, o[2]); o[3] = fmaf(p, va.w, o[3]);
            o[4] = fmaf(p, vb.x, o[4]); o[5] = fmaf(p, vb.y, o[5]);
            o[6] = fmaf(p, vb.z, o[6]); o[7] = fmaf(p, vb.w, o[7]);
        }
    }

    // merge 4 key-segments (lanes 4q..4q+3, same warp)
#pragma unroll
    for (int off = 1; off < 4; off <<= 1) {
        float m2 = __shfl_xor_sync(0xffffffffu, m, off);
        float l2 = __shfl_xor_sync(0xffffffffu, l, off);
        float o2[8];
#pragma unroll
        for (int j = 0; j < 8; j++) o2[j] = __shfl_xor_sync(0xffffffffu, o[j], off);
        float M  = fmaxf(m, m2);
        float a1 = __expf(m - M), a2 = __expf(m2 - M);
        l = l * a1 + l2 * a2;
#pragma unroll
        for (int j = 0; j < 8; j++) o[j] = o[j] * a1 + o2[j] * a2;
        m = M;
    }
    if (seg == 0) {
        float inv = 1.f / l;
        int b = bh >> 3, h = bh & 7;
        float* op = g_attp + (b * SEQ + qs) * 64 + h * 8;
#pragma unroll
        for (int j = 0; j < 8; j++) op[j] = o[j] * inv;
    }
    __syncthreads();  // smem reused next phase
}

// ---------------- oproj + FFN + k-write + combine + next QKV (8 rows) ----
__device__ __forceinline__ void tail_unit(
        int unit, int st, int step, float* __restrict__ sm,
        float* __restrict__ out,
        const float* __restrict__ Wq, const float* __restrict__ bq,
        const float* __restrict__ Wk, const float* __restrict__ bk,
        const float* __restrict__ Wv, const float* __restrict__ bv,
        const float* __restrict__ Wo, const float* __restrict__ bo,
        const float* __restrict__ W1, const float* __restrict__ b1,
        const float* __restrict__ W2, const float* __restrict__ b2) {
    float* ap    = sm;          // 512
    float* att_s = sm + 512;    // 512
    float* z_s   = sm + 1024;   // 512
    float* h_s   = sm + 1536;   // 2048
    float* ysm   = sm + 3584;   // 512

    const int tid = threadIdx.x;
    const int r0  = unit * 8;

    for (int i = tid; i < 512; i += 256) ap[i] = g_attp[r0 * 64 + i];
    __syncthreads();

    const int c  = tid & 63;
    const int rp = tid >> 6;
    const int gi0 = (r0 + 2 * rp) * 64 + c;
    const int gi1 = gi0 + 64;

    // output projection (2 rows per thread)
    float a0 = 0.f, a1v = 0.f;
#pragma unroll 8
    for (int kk = 0; kk < 64; kk++) {
        float w = Wo[kk * 64 + c];
        a0  = fmaf(ap[(2 * rp) * 64 + kk],     w, a0);
        a1v = fmaf(ap[(2 * rp + 1) * 64 + kk], w, a1v);
    }
    float bov = bo[c];
    a0 += bov; a1v += bov;
    att_s[(2 * rp) * 64 + c]     = a0;
    att_s[(2 * rp + 1) * 64 + c] = a1v;
    z_s[(2 * rp) * 64 + c]     = g_ys[gi0] + a0;
    z_s[(2 * rp + 1) * 64 + c] = g_ys[gi1] + a1v;
    __syncthreads();

    // hidden layer: one DFF column per thread, 8 rows
    {
        float hacc[8];
#pragma unroll
        for (int r = 0; r < 8; r++) hacc[r] = 0.f;
#pragma unroll 8
        for (int kk = 0; kk < 64; kk++) {
            float w = W1[kk * 256 + tid];
#pragma unroll
            for (int r = 0; r < 8; r++)
                hacc[r] = fmaf(z_s[r * 64 + kk], w, hacc[r]);
        }
        float b1v = b1[tid];
#pragma unroll
        for (int r = 0; r < 8; r++)
            h_s[r * 256 + tid] = fmaxf(hacc[r] + b1v, 0.f);
    }
    __syncthreads();

    // second FFN layer + residual -> k_stage
    float o0 = 0.f, o1 = 0.f;
#pragma unroll 8
    for (int kk = 0; kk < 256; kk++) {
        float w = W2[kk * 64 + c];
        o0 = fmaf(h_s[(2 * rp) * 256 + kk],     w, o0);
        o1 = fmaf(h_s[(2 * rp + 1) * 256 + kk], w, o1);
    }
    float b2v = b2[c];
    float k0v = att_s[(2 * rp) * 64 + c]     + o0 + b2v;
    float k1v = att_s[(2 * rp + 1) * 64 + c] + o1 + b2v;
    g_kbuf[st][gi0] = k0v;
    g_kbuf[st][gi1] = k1v;

    // combine for next stage / RK update, then next QKV
    if (st < 5) {
        float y0 = g_y[gi0], y1 = g_y[gi1];
        for (int j = 0; j < st; j++) {
            float cc = d_C[st + 1][j];
            y0 = fmaf(cc, g_kbuf[j][gi0], y0);
            y1 = fmaf(cc, g_kbuf[j][gi1], y1);
        }
        float cc = d_C[st + 1][st];
        y0 = fmaf(cc, k0v, y0);
        y1 = fmaf(cc, k1v, y1);
        g_ys[gi0] = y0; g_ys[gi1] = y1;
        ysm[(2 * rp) * 64 + c]     = y0;
        ysm[(2 * rp + 1) * 64 + c] = y1;
        __syncthreads();
        qkv_from_smem(ysm, r0, Wq, bq, Wk, bk, Wv, bv);
    } else {
        float y0 = g_y[gi0], y1 = g_y[gi1];
#pragma unroll
        for (int j = 0; j < 5; j++) {
            float cc = d_B[j];
            y0 = fmaf(cc, g_kbuf[j][gi0], y0);
            y1 = fmaf(cc, g_kbuf[j][gi1], y1);
        }
        y0 = fmaf(d_B[5], k0v, y0);
        y1 = fmaf(d_B[5], k1v, y1);
        if (step == 3) {
            out[gi0] = y0; out[gi1] = y1;
        } else {
            g_y[gi0] = y0;  g_y[gi1] = y1;
            g_ys[gi0] = y0; g_ys[gi1] = y1;
            ysm[(2 * rp) * 64 + c]     = y0;
            ysm[(2 * rp + 1) * 64 + c] = y1;
            __syncthreads();
            qkv_from_smem(ysm, r0, Wq, bq, Wk, bk, Wv, bv);
        }
    }
    __syncthreads();
}

// ---------------- the single persistent kernel ----------------
__global__ void __launch_bounds__(256, 2)
fused_ode_kernel(const float* __restrict__ x, float* __restrict__ out,
                 const float* __restrict__ Wq, const float* __restrict__ bq,
                 const float* __restrict__ Wk, const float* __restrict__ bk,
                 const float* __restrict__ Wv, const float* __restrict__ bv,
                 const float* __restrict__ Wo, const float* __restrict__ bo,
                 const float* __restrict__ W1, const float* __restrict__ b1,
                 const float* __restrict__ W2, const float* __restrict__ b2) {
    __shared__ float sm[8192];   // 32 KB, reused across phases
    unsigned gen = g_gen;
    const int tid = threadIdx.x;
    const unsigned nblk = gridDim.x;

    // initial phase: y = ys = x, first QKV
    for (int unit = blockIdx.x; unit < 256; unit += nblk) {
        int r0 = unit * 8;
        for (int i = tid; i < 512; i += 256) {
            float v = x[r0 * 64 + i];
            g_y[r0 * 64 + i]  = v;
            g_ys[r0 * 64 + i] = v;
            sm[i] = v;
        }
        __syncthreads();
        qkv_from_smem(sm, r0, Wq, bq, Wk, bk, Wv, bv);
        __syncthreads();
    }
    gsync(gen);

    for (int step = 0; step < 4; ++step) {
        for (int st = 0; st < 6; ++st) {
            for (int unit = blockIdx.x; unit < 256; unit += nblk)
                attn_unit(unit, sm);
            gsync(gen);
            for (int unit = blockIdx.x; unit < 256; unit += nblk)
                tail_unit(unit, st, step, sm, out,
                          Wq, bq, Wk, bk, Wv, bv, Wo, bo, W1, b1, W2, b2);
            if (!(step == 3 && st == 5)) gsync(gen);
        }
    }
}

// ---------------- host launcher ----------------
extern "C" void kernel_launch(void* const* d_in, const int* in_sizes, int n_in,
                              void* d_out, int out_size) {
    const float* x  = (const float*)d_in[0];
    // d_in[1] = mask: additive [B,1,S,1] broadcast over key axis -> softmax no-op
    const float* Wq = (const float*)d_in[2];
    const float* bq = (const float*)d_in[3];
    const float* Wk = (const float*)d_in[4];
    const float* bk = (const float*)d_in[5];
    const float* Wv = (const float*)d_in[6];
    const float* bv = (const float*)d_in[7];
    const float* Wo = (const float*)d_in[8];
    const float* bo = (const float*)d_in[9];
    const float* W1 = (const float*)d_in[10];
    const float* b1 = (const float*)d_in[11];
    const float* W2 = (const float*)d_in[12];
    const float* b2 = (const float*)d_in[13];
    float* out = (float*)d_out;

    int dev = 0, sms = 148;
    cudaGetDevice(&dev);
    cudaDeviceGetAttribute(&sms, cudaDevAttrMultiProcessorCount, dev);
    int nblk = sms * 2;
    if (nblk > 512) nblk = 512;

    fused_ode_kernel<<<nblk, 256>>>(x, out,
                                    Wq, bq, Wk, bk, Wv, bv,
                                    Wo, bo, W1, b1, W2, b2);
}

// round 3
// speedup vs baseline: 1.8903x; 1.2020x over previous
#include <cuda_runtime.h>

#define SEQ    512
#define NROW   2048
#define NELEM  (NROW*64)

typedef unsigned long long u64;

// ---------------- f32x2 helpers ----------------
__device__ __forceinline__ u64 ffma2(u64 a, u64 b, u64 c) {
    u64 d; asm("fma.rn.f32x2 %0, %1, %2, %3;" : "=l"(d) : "l"(a), "l"(b), "l"(c)); return d;
}
__device__ __forceinline__ u64 mul2(u64 a, u64 b) {
    u64 d; asm("mul.rn.f32x2 %0, %1, %2;" : "=l"(d) : "l"(a), "l"(b)); return d;
}
__device__ __forceinline__ u64 add2(u64 a, u64 b) {
    u64 d; asm("add.rn.f32x2 %0, %1, %2;" : "=l"(d) : "l"(a), "l"(b)); return d;
}
__device__ __forceinline__ u64 dup2(float x) {
    u64 d; asm("mov.b64 %0, {%1, %1};" : "=l"(d) : "f"(x)); return d;
}
__device__ __forceinline__ float2 unpk(u64 a) {
    float2 f; asm("mov.b64 {%0, %1}, %2;" : "=f"(f.x), "=f"(f.y) : "l"(a)); return f;
}
__device__ __forceinline__ float ex2f(float x) {
    float r; asm("ex2.approx.f32 %0, %1;" : "=f"(r) : "f"(x)); return r;
}

// ---------------- device scratch ----------------
__device__ float g_y   [NELEM];
__device__ float g_ys  [NELEM];
__device__ float g_kbuf[6][NELEM];
__device__ float g_q   [NELEM];   // [B,H,S,8]
__device__ float g_kT  [NELEM];   // [B,H,8,S]  (transposed K)
__device__ float g_v   [NELEM];   // [B,H,S,8]
__device__ float g_attp[NELEM];   // [B,S,64]

__device__ unsigned          g_cnt;
__device__ volatile unsigned g_gen;

__constant__ float d_C[6][5] = {
    {0.f,0.f,0.f,0.f,0.f},
    {(float)(0.25*0.25), 0.f,0.f,0.f,0.f},
    {(float)(0.25*3.0/32.0), (float)(0.25*9.0/32.0), 0.f,0.f,0.f},
    {(float)(0.25*1932.0/2197.0), (float)(0.25*-7200.0/2197.0),
     (float)(0.25*7296.0/2197.0), 0.f,0.f},
    {(float)(0.25*439.0/216.0), (float)(0.25*-8.0),
     (float)(0.25*3680.0/513.0), (float)(0.25*-845.0/4104.0), 0.f},
    {(float)(0.25*-8.0/27.0), (float)(0.25*2.0),
     (float)(0.25*-3544.0/2565.0), (float)(0.25*1859.0/4104.0),
     (float)(0.25*-11.0/40.0)}
};
__constant__ float d_B[6] = {
    (float)(0.25*16.0/135.0), 0.f,
    (float)(0.25*6656.0/12825.0),
    (float)(0.25*28561.0/56430.0),
    (float)(0.25*-9.0/50.0),
    (float)(0.25*2.0/55.0)
};

// ---------------- grid barrier ----------------
__device__ __forceinline__ void gsync(unsigned& gen) {
    __syncthreads();
    if (threadIdx.x == 0) {
        __threadfence();
        if (atomicAdd(&g_cnt, 1u) == gridDim.x - 1) {
            g_cnt = 0;
            __threadfence();
            g_gen = gen + 1;
        } else {
            while (g_gen == gen) __nanosleep(32);
            __threadfence();
        }
    }
    __syncthreads();
    gen++;
}

// ---------------- QKV projection from an 8x64 smem tile ----------------
__device__ __forceinline__ void qkv_from_smem(
        const float* __restrict__ ys_s, int row0,
        const float* __restrict__ Wq, const float* __restrict__ bq,
        const float* __restrict__ Wk, const float* __restrict__ bk,
        const float* __restrict__ Wv, const float* __restrict__ bv) {
    const int t = threadIdx.x;
    if (t >= 192) return;
    const int mat = t >> 6;
    const int w6  = t & 63;
    const int cq  = w6 >> 2;
    const int rp  = w6 & 3;
    const int c4  = cq * 4;
    const float* W  = (mat == 0) ? Wq : (mat == 1) ? Wk : Wv;
    const float* bb = (mat == 0) ? bq : (mat == 1) ? bk : bv;

    u64 a0x = 0, a0y = 0, a1x = 0, a1y = 0;
    const float* z0 = ys_s + (2 * rp) * 64;
    const float* z1 = z0 + 64;
#pragma unroll 8
    for (int kk = 0; kk < 64; kk++) {
        ulonglong2 w = *(const ulonglong2*)(W + kk * 64 + c4);
        u64 d0 = dup2(z0[kk]), d1 = dup2(z1[kk]);
        a0x = ffma2(d0, w.x, a0x); a0y = ffma2(d0, w.y, a0y);
        a1x = ffma2(d1, w.x, a1x); a1y = ffma2(d1, w.y, a1y);
    }
    float4 b4 = *(const float4*)(bb + c4);
    float2 p0 = unpk(a0x), p1 = unpk(a0y), p2 = unpk(a1x), p3 = unpk(a1y);
    float4 o0 = {p0.x + b4.x, p0.y + b4.y, p1.x + b4.z, p1.y + b4.w};
    float4 o1 = {p2.x + b4.x, p2.y + b4.y, p3.x + b4.z, p3.y + b4.w};

    const int gr = row0 + 2 * rp;
    const int b  = gr >> 9, s = gr & 511;
    const int h  = c4 >> 3, dd = c4 & 7;
    if (mat == 1) {   // transposed K: [b,h,dh,s]
        float* base = g_kT + ((b * 8 + h) * 8 + dd) * 512 + s;
        ((float2*)(base        ))[0] = make_float2(o0.x, o1.x);
        ((float2*)(base + 512  ))[0] = make_float2(o0.y, o1.y);
        ((float2*)(base + 1024 ))[0] = make_float2(o0.z, o1.z);
        ((float2*)(base + 1536 ))[0] = make_float2(o0.w, o1.w);
    } else {
        float* dst = ((mat == 0) ? g_q : g_v) + ((b * 8 + h) * 512 + s) * 8 + dd;
        *(float4*)(dst)     = o0;
        *(float4*)(dst + 8) = o1;
    }
}

// ---------------- attention: one (b,h,qtile-of-64) unit ----------------
__device__ __forceinline__ void attn_unit(int unit, float* __restrict__ sm) {
    float* Kt = sm;          // [8][512]
    float* Vs = sm + 4096;   // swizzled [512][8]
    const int bh  = unit >> 3;
    const int qt  = unit & 7;
    const int tid = threadIdx.x;

    {
        const float4* Ksrc = (const float4*)(g_kT + bh * 4096);
        const float4* Vsrc = (const float4*)(g_v  + bh * 4096);
        float4* Kd = (float4*)Kt;
        float4* Vd = (float4*)Vs;
        for (int i = tid; i < 1024; i += 256) {
            Kd[i] = Ksrc[i];
            Vd[i ^ ((i >> 3) & 7)] = Vsrc[i];
        }
    }
    __syncthreads();

    const int qp  = tid >> 3;
    const int seg = tid & 7;
    const int q0  = qt * 64 + 2 * qp;

    u64 qd0[8], qd1[8];
    {
        const float* qg = g_q + (bh * 512 + q0) * 8;
        const float C = 0.35355339059327373f * 1.4426950408889634f; // scale*log2(e)
#pragma unroll
        for (int j = 0; j < 8; j++) {
            qd0[j] = dup2(qg[j] * C);
            qd1[j] = dup2(qg[8 + j] * C);
        }
    }

    float m0 = -1e30f, m1 = -1e30f, l0 = 0.f, l1 = 0.f;
    u64 oa[4] = {0,0,0,0}, ob[4] = {0,0,0,0};

    for (int i = 0; i < 16; i++) {
        const int k4 = seg * 4 + 32 * i;
        u64 sA = 0, sB = 0, sC = 0, sD = 0;
#pragma unroll
        for (int j = 0; j < 8; j++) {
            ulonglong2 kv = *(const ulonglong2*)(Kt + j * 512 + k4);
            sA = ffma2(qd0[j], kv.x, sA);
            sB = ffma2(qd0[j], kv.y, sB);
            sC = ffma2(qd1[j], kv.x, sC);
            sD = ffma2(qd1[j], kv.y, sD);
        }
        float2 fA = unpk(sA), fB = unpk(sB), fC = unpk(sC), fD = unpk(sD);
        float c0 = fmaxf(fmaxf(fA.x, fA.y), fmaxf(fB.x, fB.y));
        float c1 = fmaxf(fmaxf(fC.x, fC.y), fmaxf(fD.x, fD.y));
        if (c0 > m0) {
            float al = ex2f(m0 - c0); l0 *= al; u64 ad = dup2(al);
            oa[0]=mul2(oa[0],ad); oa[1]=mul2(oa[1],ad); oa[2]=mul2(oa[2],ad); oa[3]=mul2(oa[3],ad);
            m0 = c0;
        }
        if (c1 > m1) {
            float al = ex2f(m1 - c1); l1 *= al; u64 ad = dup2(al);
            ob[0]=mul2(ob[0],ad); ob[1]=mul2(ob[1],ad); ob[2]=mul2(ob[2],ad); ob[3]=mul2(ob[3],ad);
            m1 = c1;
        }
        float p0[4], p1[4];
        p0[0]=ex2f(fA.x-m0); p0[1]=ex2f(fA.y-m0); p0[2]=ex2f(fB.x-m0); p0[3]=ex2f(fB.y-m0);
        p1[0]=ex2f(fC.x-m1); p1[1]=ex2f(fC.y-m1); p1[2]=ex2f(fD.x-m1); p1[3]=ex2f(fD.y-m1);
        l0 += (p0[0]+p0[1]) + (p0[2]+p0[3]);
        l1 += (p1[0]+p1[1]) + (p1[2]+p1[3]);
#pragma unroll
        for (int kk = 0; kk < 4; kk++) {
            int k  = k4 + kk;
            int u0 = (2 * k) ^ seg;
            ulonglong2 va = *(const ulonglong2*)(Vs + u0 * 4);
            ulonglong2 vb = *(const ulonglong2*)(Vs + (u0 ^ 1) * 4);
            u64 d0 = dup2(p0[kk]), d1 = dup2(p1[kk]);
            oa[0]=ffma2(d0,va.x,oa[0]); oa[1]=ffma2(d0,va.y,oa[1]);
            oa[2]=ffma2(d0,vb.x,oa[2]); oa[3]=ffma2(d0,vb.y,oa[3]);
            ob[0]=ffma2(d1,va.x,ob[0]); ob[1]=ffma2(d1,va.y,ob[1]);
            ob[2]=ffma2(d1,vb.x,ob[2]); ob[3]=ffma2(d1,vb.y,ob[3]);
        }
    }

    // merge 8 key-segments (lanes qp*8 .. qp*8+7 within warp)
#pragma unroll
    for (int off = 1; off < 8; off <<= 1) {
        float mm0 = __shfl_xor_sync(~0u, m0, off);
        float ll0 = __shfl_xor_sync(~0u, l0, off);
        float mm1 = __shfl_xor_sync(~0u, m1, off);
        float ll1 = __shfl_xor_sync(~0u, l1, off);
        u64 t0[4], t1[4];
#pragma unroll
        for (int j = 0; j < 4; j++) {
            t0[j] = __shfl_xor_sync(~0u, oa[j], off);
            t1[j] = __shfl_xor_sync(~0u, ob[j], off);
        }
        float M0 = fmaxf(m0, mm0), M1 = fmaxf(m1, mm1);
        float a1 = ex2f(m0 - M0), a2 = ex2f(mm0 - M0);
        float b1v = ex2f(m1 - M1), b2v = ex2f(mm1 - M1);
        l0 = l0 * a1 + ll0 * a2;
        l1 = l1 * b1v + ll1 * b2v;
        u64 A1 = dup2(a1), A2 = dup2(a2), B1 = dup2(b1v), B2 = dup2(b2v);
#pragma unroll
        for (int j = 0; j < 4; j++) {
            oa[j] = ffma2(t0[j], A2, mul2(oa[j], A1));
            ob[j] = ffma2(t1[j], B2, mul2(ob[j], B1));
        }
        m0 = M0; m1 = M1;
    }

    if (seg == 0) {
        float inv0 = 1.f / l0, inv1 = 1.f / l1;
        const int b = bh >> 3, h = bh & 7;
        float* op = g_attp + (b * 512 + q0) * 64 + h * 8;
        float2 x0 = unpk(oa[0]), x1 = unpk(oa[1]), x2 = unpk(oa[2]), x3 = unpk(oa[3]);
        ((float4*)op)[0] = make_float4(x0.x*inv0, x0.y*inv0, x1.x*inv0, x1.y*inv0);
        ((float4*)op)[1] = make_float4(x2.x*inv0, x2.y*inv0, x3.x*inv0, x3.y*inv0);
        float2 y0 = unpk(ob[0]), y1 = unpk(ob[1]), y2 = unpk(ob[2]), y3 = unpk(ob[3]);
        float* oq = op + 64;
        ((float4*)oq)[0] = make_float4(y0.x*inv1, y0.y*inv1, y1.x*inv1, y1.y*inv1);
        ((float4*)oq)[1] = make_float4(y2.x*inv1, y2.y*inv1, y3.x*inv1, y3.y*inv1);
    }
    __syncthreads();
}

// ---------------- tail: oproj + FFN + k-write + combine + next QKV ----------------
__device__ __forceinline__ void tail_unit(
        int unit, int st, int step, float* __restrict__ sm,
        float* __restrict__ out,
        const float* __restrict__ Wq, const float* __restrict__ bq,
        const float* __restrict__ Wk, const float* __restrict__ bk,
        const float* __restrict__ Wv, const float* __restrict__ bv,
        const float* __restrict__ Wo, const float* __restrict__ bo,
        const float* __restrict__ W1, const float* __restrict__ b1,
        const float* __restrict__ W2, const float* __restrict__ b2) {
    float* ap   = sm;            // 512
    float* atts = sm + 512;      // 512
    float* z_s  = sm + 1024;     // 512
    float* h_s  = sm + 1536;     // 2048
    float* ysm  = sm + 3584;     // 512

    const int tid = threadIdx.x;
    const int r0  = unit * 8;

    for (int i = tid; i < 128; i += 256)
        ((float4*)ap)[i] = ((const float4*)(g_attp + r0 * 64))[i];
    __syncthreads();

    const int r  = tid >> 5;        // 0..7
    const int kh = (tid >> 4) & 1;  // k-half
    const int cq = tid & 15;
    const int c4 = cq * 4;

    // ---- output projection ----
    {
        u64 ax = 0, ay = 0;
        const float* aprow = ap + r * 64;
        const int k0 = kh * 32;
#pragma unroll 8
        for (int kk = k0; kk < k0 + 32; kk++) {
            ulonglong2 w = *(const ulonglong2*)(Wo + kk * 64 + c4);
            u64 d = dup2(aprow[kk]);
            ax = ffma2(d, w.x, ax);
            ay = ffma2(d, w.y, ay);
        }
        ax = add2(ax, __shfl_xor_sync(~0u, ax, 16));
        ay = add2(ay, __shfl_xor_sync(~0u, ay, 16));
        if (kh == 0) {
            float2 f0 = unpk(ax), f1 = unpk(ay);
            float4 b4 = *(const float4*)(bo + c4);
            float4 a = {f0.x + b4.x, f0.y + b4.y, f1.x + b4.z, f1.y + b4.w};
            *(float4*)(atts + r * 64 + c4) = a;
            float4 ys4 = *(const float4*)(g_ys + (r0 + r) * 64 + c4);
            float4 z = {a.x + ys4.x, a.y + ys4.y, a.z + ys4.z, a.w + ys4.w};
            *(float4*)(z_s + r * 64 + c4) = z;
        }
    }
    __syncthreads();

    // ---- FFN layer 1 ----
    {
        const int cf = (tid & 63) * 4;
        const int rp = tid >> 6;
        u64 a0x = 0, a0y = 0, a1x = 0, a1y = 0;
        const float* z0 = z_s + (2 * rp) * 64;
        const float* z1 = z0 + 64;
#pragma unroll 8
        for (int kk = 0; kk < 64; kk++) {
            ulonglong2 w = *(const ulonglong2*)(W1 + kk * 256 + cf);
            u64 d0 = dup2(z0[kk]), d1 = dup2(z1[kk]);
            a0x = ffma2(d0, w.x, a0x); a0y = ffma2(d0, w.y, a0y);
            a1x = ffma2(d1, w.x, a1x); a1y = ffma2(d1, w.y, a1y);
        }
        float4 b4 = *(const float4*)(b1 + cf);
        float2 u0 = unpk(a0x), u1 = unpk(a0y), u2 = unpk(a1x), u3 = unpk(a1y);
        *(float4*)(h_s + (2 * rp) * 256 + cf) =
            make_float4(fmaxf(u0.x + b4.x, 0.f), fmaxf(u0.y + b4.y, 0.f),
                        fmaxf(u1.x + b4.z, 0.f), fmaxf(u1.y + b4.w, 0.f));
        *(float4*)(h_s + (2 * rp + 1) * 256 + cf) =
            make_float4(fmaxf(u2.x + b4.x, 0.f), fmaxf(u2.y + b4.y, 0.f),
                        fmaxf(u3.x + b4.z, 0.f), fmaxf(u3.y + b4.w, 0.f));
    }
    __syncthreads();

    // ---- FFN layer 2 + residual + RK combine ----
    {
        u64 ax = 0, ay = 0;
        const float* hrow = h_s + r * 256;
        const int k0 = kh * 128;
#pragma unroll 8
        for (int kk = k0; kk < k0 + 128; kk++) {
            ulonglong2 w = *(const ulonglong2*)(W2 + kk * 64 + c4);
            u64 d = dup2(hrow[kk]);
            ax = ffma2(d, w.x, ax);
            ay = ffma2(d, w.y, ay);
        }
        ax = add2(ax, __shfl_xor_sync(~0u, ax, 16));
        ay = add2(ay, __shfl_xor_sync(~0u, ay, 16));
        if (kh == 0) {
            float2 f0 = unpk(ax), f1 = unpk(ay);
            float4 b4  = *(const float4*)(b2 + c4);
            float4 at4 = *(const float4*)(atts + r * 64 + c4);
            float4 kv = {at4.x + f0.x + b4.x, at4.y + f0.y + b4.y,
                         at4.z + f1.x + b4.z, at4.w + f1.y + b4.w};
            const int gi = (r0 + r) * 64 + c4;
            *(float4*)(g_kbuf[st] + gi) = kv;

            float4 y = *(const float4*)(g_y + gi);
            if (st < 5) {
                for (int j = 0; j < st; j++) {
                    float cc = d_C[st + 1][j];
                    float4 kj = *(const float4*)(g_kbuf[j] + gi);
                    y.x = fmaf(cc, kj.x, y.x); y.y = fmaf(cc, kj.y, y.y);
                    y.z = fmaf(cc, kj.z, y.z); y.w = fmaf(cc, kj.w, y.w);
                }
                float cc = d_C[st + 1][st];
                y.x = fmaf(cc, kv.x, y.x); y.y = fmaf(cc, kv.y, y.y);
                y.z = fmaf(cc, kv.z, y.z); y.w = fmaf(cc, kv.w, y.w);
                *(float4*)(g_ys + gi) = y;
                *(float4*)(ysm + r * 64 + c4) = y;
            } else {
                for (int j = 0; j < 5; j++) {
                    float cc = d_B[j];
                    float4 kj = *(const float4*)(g_kbuf[j] + gi);
                    y.x = fmaf(cc, kj.x, y.x); y.y = fmaf(cc, kj.y, y.y);
                    y.z = fmaf(cc, kj.z, y.z); y.w = fmaf(cc, kj.w, y.w);
                }
                float cc = d_B[5];
                y.x = fmaf(cc, kv.x, y.x); y.y = fmaf(cc, kv.y, y.y);
                y.z = fmaf(cc, kv.z, y.z); y.w = fmaf(cc, kv.w, y.w);
                if (step == 3) {
                    *(float4*)(out + gi) = y;
                } else {
                    *(float4*)(g_y  + gi) = y;
                    *(float4*)(g_ys + gi) = y;
                    *(float4*)(ysm + r * 64 + c4) = y;
                }
            }
        }
    }
    __syncthreads();
    if (!(st == 5 && step == 3))
        qkv_from_smem(ysm, r0, Wq, bq, Wk, bk, Wv, bv);
    __syncthreads();
}

// ---------------- persistent kernel ----------------
__global__ void __launch_bounds__(256, 2)
fused_ode_kernel(const float* __restrict__ x, float* __restrict__ out,
                 const float* __restrict__ Wq, const float* __restrict__ bq,
                 const float* __restrict__ Wk, const float* __restrict__ bk,
                 const float* __restrict__ Wv, const float* __restrict__ bv,
                 const float* __restrict__ Wo, const float* __restrict__ bo,
                 const float* __restrict__ W1, const float* __restrict__ b1,
                 const float* __restrict__ W2, const float* __restrict__ b2) {
    __shared__ float sm[8192];
    unsigned gen = g_gen;
    const int tid = threadIdx.x;
    const unsigned nblk = gridDim.x;

    for (int unit = blockIdx.x; unit < 256; unit += nblk) {
        const int r0 = unit * 8;
        for (int i = tid; i < 128; i += 256) {
            float4 v = ((const float4*)(x + r0 * 64))[i];
            ((float4*)(g_y  + r0 * 64))[i] = v;
            ((float4*)(g_ys + r0 * 64))[i] = v;
            ((float4*)sm)[i] = v;
        }
        __syncthreads();
        qkv_from_smem(sm, r0, Wq, bq, Wk, bk, Wv, bv);
        __syncthreads();
    }
    gsync(gen);

    for (int step = 0; step < 4; ++step) {
        for (int st = 0; st < 6; ++st) {
            for (int unit = blockIdx.x; unit < 256; unit += nblk)
                attn_unit(unit, sm);
            gsync(gen);
            for (int unit = blockIdx.x; unit < 256; unit += nblk)
                tail_unit(unit, st, step, sm, out,
                          Wq, bq, Wk, bk, Wv, bv, Wo, bo, W1, b1, W2, b2);
            if (!(step == 3 && st == 5)) gsync(gen);
        }
    }
}

// ---------------- host launcher ----------------
extern "C" void kernel_launch(void* const* d_in, const int* in_sizes, int n_in,
                              void* d_out, int out_size) {
    const float* x  = (const float*)d_in[0];
    // d_in[1] = mask: additive [B,1,S,1] broadcast over key axis -> softmax no-op
    const float* Wq = (const float*)d_in[2];
    const float* bq = (const float*)d_in[3];
    const float* Wk = (const float*)d_in[4];
    const float* bk = (const float*)d_in[5];
    const float* Wv = (const float*)d_in[6];
    const float* bv = (const float*)d_in[7];
    const float* Wo = (const float*)d_in[8];
    const float* bo = (const float*)d_in[9];
    const float* W1 = (const float*)d_in[10];
    const float* b1 = (const float*)d_in[11];
    const float* W2 = (const float*)d_in[12];
    const float* b2 = (const float*)d_in[13];
    float* out = (float*)d_out;

    int dev = 0, sms = 148;
    cudaGetDevice(&dev);
    cudaDeviceGetAttribute(&sms, cudaDevAttrMultiProcessorCount, dev);
    int nblk = sms * 2;
    if (nblk > 512) nblk = 512;

    fused_ode_kernel<<<nblk, 256>>>(x, out,
                                    Wq, bq, Wk, bk, Wv, bv,
                                    Wo, bo, W1, b1, W2, b2);
}